// round 7
// baseline (speedup 1.0000x reference)
#include <cuda_runtime.h>
#include <cstdint>

#define W_DIM 81920
#define N_DIM 4
#define C_DIM 64
#define O_DIM 64
#define K_DIM 10
#define TILE_W 256
#define TILES_PER_N (W_DIM / TILE_W)            // 320
#define NTILES      (N_DIM * TILES_PER_N)       // 1280
#define TBL_ELEMS   (W_DIM * K_DIM)             // 819200
#define PHASES 10                               // one per k
#define STEPS  16                               // c/4 per phase
#define GP 17                                   // gather pitch (float4)
#define WPIT 65                                 // weight pitch (float4)
#define GBUF (TILE_W * GP)                      // 4352 f4
#define WBUF (STEPS * WPIT)                     // 1040 f4
#define STAGE_F4 (GBUF + WBUF)                  // 5392 f4 = 86272 B
#define SMEM_BYTES (2 * STAGE_F4 * 16 + TILE_W * K_DIM * 4)  // 182784 B

// Static device scratch (no runtime allocation)
__device__ float g_xT[(size_t)N_DIM * W_DIM * C_DIM];  // input transposed [N,W,C]
__device__ float g_w4[O_DIM * C_DIM * K_DIM];          // weight, phase-major f4 layout
__device__ int   g_idx[TBL_ELEMS];                     // canonical int32 gather table
__device__ int   g_is_i32;

// ---------------------------------------------------------------------------
// conv_table dtype detection (reference says int64; JAX x64-off gives int32).
__global__ void detect_kernel(const int* __restrict__ t32) {
    __shared__ int f;
    if (threadIdx.x == 0) f = 0;
    __syncthreads();
    if (t32[2 * threadIdx.x + 1] != 0) atomicOr(&f, 1);
    __syncthreads();
    if (threadIdx.x == 0) g_is_i32 = f;
}

__global__ void convert_kernel(const int* __restrict__ t32) {
    int i = blockIdx.x * 256 + threadIdx.x;
    if (i < TBL_ELEMS)
        g_idx[i] = g_is_i32 ? t32[i] : t32[2 * i];
}

// ---------------------------------------------------------------------------
// input [N,C,W] -> g_xT [N,W,C]
__global__ void transpose_kernel(const float* __restrict__ in) {
    __shared__ float t[32][33];
    int n  = blockIdx.z;
    int c0 = blockIdx.y << 5;
    int w0 = blockIdx.x << 5;
    int tx = threadIdx.x, ty = threadIdx.y;

    const size_t inb = ((size_t)n * C_DIM + c0) * W_DIM + w0;
#pragma unroll
    for (int i = 0; i < 32; i += 8)
        t[ty + i][tx] = in[inb + (size_t)(ty + i) * W_DIM + tx];
    __syncthreads();
    const size_t ob = ((size_t)n * W_DIM + w0) * C_DIM + c0;
#pragma unroll
    for (int i = 0; i < 32; i += 8)
        g_xT[ob + (size_t)(ty + i) * C_DIM + tx] = t[tx][ty + i];
}

// ---------------------------------------------------------------------------
// weight [O,C,K,1] -> g_w4: f4 chunk (k*16 + c/4)*64 + o, component c&3.
__global__ void wprep_kernel(const float* __restrict__ w) {
    int i = blockIdx.x * 256 + threadIdx.x;
    if (i < O_DIM * C_DIM * K_DIM) {
        int o = i / (C_DIM * K_DIM);
        int r = i - o * (C_DIM * K_DIM);
        int c = r / K_DIM;
        int k = r - c * K_DIM;
        g_w4[(((k * 16) + (c >> 2)) * O_DIM + o) * 4 + (c & 3)] = w[i];
    }
}

// ---------------------------------------------------------------------------
// Main kernel: tile 256w x 64o, 10 k-phases, cp.async double buffer,
// 8w x 8o register tile per thread (f32x2 packed over c-pairs).
// wq = tid&31 (w mod 32), og = tid>>5 (o-octet).
// ---------------------------------------------------------------------------
__global__ void __launch_bounds__(256, 1)
conv_kernel(const float* __restrict__ bias,
            float* __restrict__ out) {
    extern __shared__ float4 smem4[];
    float4* buf0  = smem4;
    float4* buf1  = smem4 + STAGE_F4;
    int*    s_idx = (int*)(smem4 + 2 * STAGE_F4);   // [k][row] = [10][256]

    const int tid = threadIdx.x;
    const int wq  = tid & 31;
    const int og  = tid >> 5;                        // 0..7, o = og*8 .. og*8+7

    const unsigned sbase = (unsigned)__cvta_generic_to_shared(smem4);
    const unsigned sidxb = (unsigned)__cvta_generic_to_shared(s_idx);

    float b[8];
#pragma unroll
    for (int r = 0; r < 8; ++r) b[r] = bias[og * 8 + r];

    const int row0 = tid >> 4;      // gather: base row (0..15)
    const int c4   = tid & 15;      // gather: channel f4 chunk

    for (int t = blockIdx.x; t < NTILES; t += gridDim.x) {
        const int n  = t / TILES_PER_N;
        const int w0 = (t - n * TILES_PER_N) * TILE_W;
        const float* xTn = g_xT + (size_t)n * W_DIM * C_DIM;

        // ---- per-tile index preload into [k][row] layout ----
#pragma unroll
        for (int i = 0; i < PHASES; ++i) {
            int lin = tid + 256 * i;                // 0..2559
            int row = lin / K_DIM;
            int k   = lin - row * K_DIM;
            s_idx[k * TILE_W + row] = g_idx[w0 * K_DIM + lin];
        }
        __syncthreads();

        // ---- cp.async loader for one phase into stage s (0/1) ----
        auto issue_phase = [&](int p, int s) {
            const unsigned sb = sbase + s * (STAGE_F4 * 16);
            // gather: 16 chunks of 16B (rows row0+16j, chunk c4)
#pragma unroll
            for (int j = 0; j < 16; ++j) {
                int row = row0 + 16 * j;
                int idx = s_idx[p * TILE_W + row];
                unsigned sa = sb + (unsigned)(row * GP + c4) * 16u;
                const float* ga = xTn + (size_t)idx * C_DIM + c4 * 4;
                asm volatile("cp.async.cg.shared.global [%0], [%1], 16;\n"
                             :: "r"(sa), "l"(ga) : "memory");
            }
            // weight slice: 4 chunks
            const float4* w4 = reinterpret_cast<const float4*>(g_w4) + p * (STEPS * O_DIM);
#pragma unroll
            for (int i = 0; i < 4; ++i) {
                int lin = tid + 256 * i;            // 0..1023
                int cq  = lin >> 6;
                int o   = lin & 63;
                unsigned sa = sb + (unsigned)(GBUF + cq * WPIT + o) * 16u;
                asm volatile("cp.async.cg.shared.global [%0], [%1], 16;\n"
                             :: "r"(sa), "l"(w4 + lin) : "memory");
            }
            asm volatile("cp.async.commit_group;\n" ::: "memory");
        };

        // ---- prologue: phase 0 ----
        issue_phase(0, 0);
        asm volatile("cp.async.wait_group 0;\n" ::: "memory");
        __syncthreads();

        unsigned long long acc[8][8];
#pragma unroll
        for (int i = 0; i < 8; ++i)
#pragma unroll
            for (int r = 0; r < 8; ++r) acc[i][r] = 0ull;

        // ---- phase loop ----
        for (int p = 0; p < PHASES; ++p) {
            if (p < PHASES - 1) issue_phase(p + 1, (p + 1) & 1);

            const float4* cb = (p & 1) ? buf1 : buf0;
#pragma unroll 4
            for (int cq = 0; cq < STEPS; ++cq) {
                ulonglong2 g[8];
#pragma unroll
                for (int i = 0; i < 8; ++i)
                    g[i] = *reinterpret_cast<const ulonglong2*>(cb + (wq + 32 * i) * GP + cq);
#pragma unroll
                for (int h = 0; h < 2; ++h) {
                    ulonglong2 wt[4];
#pragma unroll
                    for (int r = 0; r < 4; ++r)
                        wt[r] = *reinterpret_cast<const ulonglong2*>(
                            cb + GBUF + cq * WPIT + og * 8 + h * 4 + r);
#pragma unroll
                    for (int i = 0; i < 8; ++i)
#pragma unroll
                        for (int r = 0; r < 4; ++r) {
                            asm("fma.rn.f32x2 %0, %1, %2, %0;"
                                : "+l"(acc[i][h * 4 + r]) : "l"(g[i].x), "l"(wt[r].x));
                            asm("fma.rn.f32x2 %0, %1, %2, %0;"
                                : "+l"(acc[i][h * 4 + r]) : "l"(g[i].y), "l"(wt[r].y));
                        }
                }
            }

            if (p < PHASES - 1)
                asm volatile("cp.async.wait_group 0;\n" ::: "memory");
            __syncthreads();
        }

        // ---- epilogue: reduce halves, bias, relu, store ----
#pragma unroll
        for (int r = 0; r < 8; ++r) {
            const size_t ob = ((size_t)n * O_DIM + og * 8 + r) * W_DIM + w0;
#pragma unroll
            for (int i = 0; i < 8; ++i) {
                unsigned long long v = acc[i][r];
                float s = __uint_as_float((unsigned)v) +
                          __uint_as_float((unsigned)(v >> 32));
                out[ob + wq + 32 * i] = fmaxf(s + b[r], 0.0f);
            }
        }
        // next tile's s_idx STS is safe: last phase ended with __syncthreads()
    }
    (void)sidxb;
}

// ---------------------------------------------------------------------------
extern "C" void kernel_launch(void* const* d_in, const int* in_sizes, int n_in,
                              void* d_out, int out_size) {
    const float* input  = (const float*)d_in[0];
    const int*   tbl32  = (const int*)d_in[1];
    const float* weight = (const float*)d_in[2];
    const float* bias   = (const float*)d_in[3];
    float*       out    = (float*)d_out;

    cudaFuncSetAttribute(conv_kernel,
                         cudaFuncAttributeMaxDynamicSharedMemorySize, SMEM_BYTES);

    int dev = 0;
    cudaGetDevice(&dev);
    int nsm = 148;
    cudaDeviceGetAttribute(&nsm, cudaDevAttrMultiProcessorCount, dev);

    detect_kernel<<<1, 64>>>(tbl32);
    convert_kernel<<<(TBL_ELEMS + 255) / 256, 256>>>(tbl32);
    transpose_kernel<<<dim3(W_DIM / 32, C_DIM / 32, N_DIM), dim3(32, 8)>>>(input);
    wprep_kernel<<<(O_DIM * C_DIM * K_DIM + 255) / 256, 256>>>(weight);
    conv_kernel<<<nsm, 256, SMEM_BYTES>>>(bias, out);
}

// round 10
// speedup vs baseline: 2.4846x; 2.4846x over previous
#include <cuda_runtime.h>
#include <cstdint>

#define W_DIM 81920
#define N_DIM 4
#define C_DIM 64
#define O_DIM 64
#define K_DIM 10
#define TILE_W 128
#define TILES_PER_N (W_DIM / TILE_W)            // 640
#define NTILES      (N_DIM * TILES_PER_N)       // 2560
#define TBL_ELEMS   (W_DIM * K_DIM)             // 819200
#define PHASES 10
#define PITCHF 68                               // floats per smem row (272 B)
#define PITCHB (PITCHF * 4)                     // 272
#define A_BYTES (TILE_W * PITCHB)               // 34816
#define B_BYTES (O_DIM * PITCHB)                // 17408
#define STAGE_BYTES (A_BYTES + B_BYTES)         // 52224
#define SM_BIAS 0
#define SM_STAGE 256
#define SMEM_BYTES (SM_STAGE + 2 * STAGE_BYTES) // 104704

// Static device scratch (no runtime allocation)
__device__ float g_xT[(size_t)N_DIM * W_DIM * C_DIM];  // [N,W,C], tf32-rounded
__device__ float g_wB[K_DIM * O_DIM * C_DIM];          // [k][o][c], tf32-rounded
__device__ int   g_idxT[TBL_ELEMS];                    // gather table [k][w]
__device__ int   g_is_i32;

__device__ __forceinline__ float to_tf32(float x) {
    asm("cvt.rna.tf32.f32 %0, %1;" : "=f"(x) : "f"(x));
    return x;
}

// ---------------------------------------------------------------------------
__global__ void detect_kernel(const int* __restrict__ t32) {
    __shared__ int f;
    if (threadIdx.x == 0) f = 0;
    __syncthreads();
    if (t32[2 * threadIdx.x + 1] != 0) atomicOr(&f, 1);
    __syncthreads();
    if (threadIdx.x == 0) g_is_i32 = f;
}

__global__ void convert_kernel(const int* __restrict__ t32) {
    int i = blockIdx.x * 256 + threadIdx.x;
    if (i < TBL_ELEMS) {
        int v = g_is_i32 ? t32[i] : t32[2 * i];
        int w = i / K_DIM;
        int k = i - w * K_DIM;
        g_idxT[k * W_DIM + w] = v;
    }
}

// input [N,C,W] -> g_xT [N,W,C] (tf32-rounded)
__global__ void transpose_kernel(const float* __restrict__ in) {
    __shared__ float t[32][33];
    int n  = blockIdx.z;
    int c0 = blockIdx.y << 5;
    int w0 = blockIdx.x << 5;
    int tx = threadIdx.x, ty = threadIdx.y;

    const size_t inb = ((size_t)n * C_DIM + c0) * W_DIM + w0;
#pragma unroll
    for (int i = 0; i < 32; i += 8)
        t[ty + i][tx] = in[inb + (size_t)(ty + i) * W_DIM + tx];
    __syncthreads();
    const size_t ob = ((size_t)n * W_DIM + w0) * C_DIM + c0;
#pragma unroll
    for (int i = 0; i < 32; i += 8)
        g_xT[ob + (size_t)(ty + i) * C_DIM + tx] = to_tf32(t[tx][ty + i]);
}

// weight [O,C,K,1] -> g_wB [k][o][c] (tf32-rounded)
__global__ void wprep_kernel(const float* __restrict__ w) {
    int i = blockIdx.x * 256 + threadIdx.x;
    if (i < O_DIM * C_DIM * K_DIM) {
        int o = i / (C_DIM * K_DIM);
        int r = i - o * (C_DIM * K_DIM);
        int c = r / K_DIM;
        int k = r - c * K_DIM;
        g_wB[(k * O_DIM + o) * C_DIM + c] = to_tf32(w[i]);
    }
}

// ---------------------------------------------------------------------------
// Conv: tile 128w x 64o, cp.async double-buffered phases, tf32 mma.sync.
// 256 threads = 8 warps in 4(m) x 2(n) grid, each warp computes 32x32.
// ---------------------------------------------------------------------------
__global__ void __launch_bounds__(256, 2)
conv_kernel(const float* __restrict__ bias, float* __restrict__ out) {
    extern __shared__ char smem[];
    const unsigned sb = (unsigned)__cvta_generic_to_shared(smem);

    const int tid  = threadIdx.x;
    const int wid  = tid >> 5;
    const int lane = tid & 31;
    const int wr   = wid >> 1;          // warp row 0..3 (m)
    const int wn   = wid & 1;           // warp col 0..1 (n)

    if (tid < O_DIM)
        *reinterpret_cast<float*>(smem + SM_BIAS + tid * 4) = bias[tid];

    // ldmatrix per-lane address offsets (within a stage)
    const int lr  = lane & 7;           // row within 8-row matrix
    const int lm  = lane >> 3;          // matrix id 0..3
    unsigned aoff[2], boff[4];
#pragma unroll
    for (int mt = 0; mt < 2; ++mt)
        aoff[mt] = (unsigned)((wr * 32 + mt * 16 + lr + (lm & 1) * 8) * PITCHB
                              + (lm >> 1) * 16);
#pragma unroll
    for (int nt = 0; nt < 4; ++nt)
        boff[nt] = (unsigned)(A_BYTES + (wn * 32 + nt * 8 + lr) * PITCHB
                              + (lm & 1) * 16);

    // epilogue lane mapping (mma C layout)
    const int g2 = lane >> 2;           // C row within 8
    const int tg = lane & 3;            // C col pair

    const int arow = tid >> 4;          // loader helpers
    const int ac4  = tid & 15;
    __syncthreads();

    for (int t = blockIdx.x; t < NTILES; t += gridDim.x) {
        const int n  = t / TILES_PER_N;
        const int w0 = (t - n * TILES_PER_N) * TILE_W;
        const float* xTn = g_xT + (size_t)n * W_DIM * C_DIM;

        // ---- cp.async loader: phase p into stage s ----
        auto issue = [&](int p, int s) {
            const unsigned stg = sb + SM_STAGE + (unsigned)s * STAGE_BYTES;
            const int* idxp = g_idxT + p * W_DIM + w0;
#pragma unroll
            for (int j = 0; j < 8; ++j) {           // A: 2048 16B chunks
                int row = arow + 16 * j;
                int idx = idxp[row];
                unsigned sa = stg + (unsigned)(row * PITCHB + ac4 * 16);
                const float* ga = xTn + (size_t)idx * C_DIM + ac4 * 4;
                asm volatile("cp.async.cg.shared.global [%0], [%1], 16;"
                             :: "r"(sa), "l"(ga) : "memory");
            }
            const float* wp = g_wB + p * (O_DIM * C_DIM);
#pragma unroll
            for (int j = 0; j < 4; ++j) {           // B: 1024 16B chunks
                int lin = tid + 256 * j;
                int o   = lin >> 4;
                int c4  = lin & 15;
                unsigned sa = stg + (unsigned)(A_BYTES + o * PITCHB + c4 * 16);
                asm volatile("cp.async.cg.shared.global [%0], [%1], 16;"
                             :: "r"(sa), "l"(wp + o * C_DIM + c4 * 4) : "memory");
            }
            asm volatile("cp.async.commit_group;" ::: "memory");
        };

        issue(0, 0);

        float acc[2][4][4];
#pragma unroll
        for (int mt = 0; mt < 2; ++mt)
#pragma unroll
            for (int nt = 0; nt < 4; ++nt)
#pragma unroll
                for (int r = 0; r < 4; ++r) acc[mt][nt][r] = 0.0f;

        for (int p = 0; p < PHASES; ++p) {
            if (p < PHASES - 1) {
                issue(p + 1, (p + 1) & 1);
                asm volatile("cp.async.wait_group 1;" ::: "memory");
            } else {
                asm volatile("cp.async.wait_group 0;" ::: "memory");
            }
            __syncthreads();   // stage (p&1) fully visible

            const unsigned stg = sb + SM_STAGE + (unsigned)(p & 1) * STAGE_BYTES;
#pragma unroll
            for (int kk = 0; kk < 8; ++kk) {
                const unsigned kb = kk * 32;
                uint32_t a[2][4], b[4][2];
#pragma unroll
                for (int mt = 0; mt < 2; ++mt)
                    asm volatile(
                        "ldmatrix.sync.aligned.m8n8.x4.shared.b16 {%0,%1,%2,%3}, [%4];"
                        : "=r"(a[mt][0]), "=r"(a[mt][1]), "=r"(a[mt][2]), "=r"(a[mt][3])
                        : "r"(stg + aoff[mt] + kb));
#pragma unroll
                for (int nt = 0; nt < 4; ++nt)
                    asm volatile(
                        "ldmatrix.sync.aligned.m8n8.x2.shared.b16 {%0,%1}, [%2];"
                        : "=r"(b[nt][0]), "=r"(b[nt][1])
                        : "r"(stg + boff[nt] + kb));
#pragma unroll
                for (int mt = 0; mt < 2; ++mt)
#pragma unroll
                    for (int nt = 0; nt < 4; ++nt)
                        asm volatile(
                            "mma.sync.aligned.m16n8k8.row.col.f32.tf32.tf32.f32 "
                            "{%0,%1,%2,%3}, {%4,%5,%6,%7}, {%8,%9}, {%0,%1,%2,%3};"
                            : "+f"(acc[mt][nt][0]), "+f"(acc[mt][nt][1]),
                              "+f"(acc[mt][nt][2]), "+f"(acc[mt][nt][3])
                            : "r"(a[mt][0]), "r"(a[mt][1]), "r"(a[mt][2]), "r"(a[mt][3]),
                              "r"(b[nt][0]), "r"(b[nt][1]));
            }
            __syncthreads();   // all reads of stage (p&1) done before overwrite
        }

        // ---- epilogue: bias + relu + scattered-but-sectored stores ----
        const float* sbias = reinterpret_cast<const float*>(smem + SM_BIAS);
#pragma unroll
        for (int nt = 0; nt < 4; ++nt) {
            const int o0 = wn * 32 + nt * 8 + 2 * tg;
            const float bz0 = sbias[o0], bz1 = sbias[o0 + 1];
            const size_t ob0 = ((size_t)n * O_DIM + o0) * W_DIM + w0;
            const size_t ob1 = ob0 + W_DIM;
#pragma unroll
            for (int mt = 0; mt < 2; ++mt) {
                const int wrow = wr * 32 + mt * 16 + g2;
                out[ob0 + wrow]     = fmaxf(acc[mt][nt][0] + bz0, 0.0f);
                out[ob1 + wrow]     = fmaxf(acc[mt][nt][1] + bz1, 0.0f);
                out[ob0 + wrow + 8] = fmaxf(acc[mt][nt][2] + bz0, 0.0f);
                out[ob1 + wrow + 8] = fmaxf(acc[mt][nt][3] + bz1, 0.0f);
            }
        }
        // next issue(0,0) overwrites stage0: last read at p=8, guarded by its
        // trailing __syncthreads(); stage1 guarded by p=9's trailing sync.
    }
}

// ---------------------------------------------------------------------------
extern "C" void kernel_launch(void* const* d_in, const int* in_sizes, int n_in,
                              void* d_out, int out_size) {
    const float* input  = (const float*)d_in[0];
    const int*   tbl32  = (const int*)d_in[1];
    const float* weight = (const float*)d_in[2];
    const float* bias   = (const float*)d_in[3];
    float*       out    = (float*)d_out;

    cudaFuncSetAttribute(conv_kernel,
                         cudaFuncAttributeMaxDynamicSharedMemorySize, SMEM_BYTES);

    int dev = 0;
    cudaGetDevice(&dev);
    int nsm = 148;
    cudaDeviceGetAttribute(&nsm, cudaDevAttrMultiProcessorCount, dev);

    detect_kernel<<<1, 64>>>(tbl32);
    convert_kernel<<<(TBL_ELEMS + 255) / 256, 256>>>(tbl32);
    transpose_kernel<<<dim3(W_DIM / 32, C_DIM / 32, N_DIM), dim3(32, 8)>>>(input);
    wprep_kernel<<<(O_DIM * C_DIM * K_DIM + 255) / 256, 256>>>(weight);
    conv_kernel<<<2 * nsm, 256, SMEM_BYTES>>>(bias, out);
}